// round 17
// baseline (speedup 1.0000x reference)
#include <cuda_runtime.h>
#include <cuda_fp16.h>
#include <cuda_bf16.h>

// ---------------------------------------------------------------------------
// GAT layer, CSR-sorted + tensor-core (mma.sync bf16x3) formulation:
//   hs = feat_src@W_src+b ; hd = feat_dst@W_dst+b
//   D = Ahi@Whi + Alo@Whi + Ahi@Wlo  (missing Alo@Wlo ~2^-18 relative).
//   BOTH GEMMs in one launch, grid (nblk, 2); dst histogram fused as a
//   grid-stride tail (rides the wave tail; int4-vectorized idx loads).
//   CSR scan: scan1 computes block-local offsets + block sums; consumers
//   (scatter, agg) redundantly scan the 196 block sums in smem -> no
//   scan2/3 launches. Edge kernels vectorize index loads (LSU-issue bound:
//   ~1.82 cyc/LDG instr is the binding floor, so fewer LDG instr = faster).
//   el/er fused into the GEMM epilogue; hd never materialized; hs fp16.
//   out[d] = sum_e hs[src_e]*w_e / sum_e w_e, w_e = exp(lrelu(el+er)).
//   Softmax max-subtraction cancels exactly. Index width self-detected.
// ---------------------------------------------------------------------------

#define NSRC 50000
#define NDST 50000
#define EMAX 1600000

typedef unsigned int uint;

__device__ __align__(16) __half g_hs_h[NSRC * 128];          // fp16 messages
__device__ __align__(16) float g_el[NSRC * 8];
__device__ __align__(16) float g_er[NDST * 8];
__device__ __align__(16) __nv_bfloat16 g_wn[2 * 128 * 256];  // [sel][n][hi|lo]
__device__ int g_sorted_src[EMAX];
__device__ int g_counts[NDST];
__device__ int g_offsets[NDST];   // block-local exclusive offsets
__device__ int g_cursors[NDST];
__device__ int g_aux[256];        // per-256-block sums from scan1

__device__ __forceinline__ float lrelu(float x) { return x >= 0.f ? x : 0.2f * x; }

__device__ __forceinline__ uint pack_bf2(float x, float y) {
    __nv_bfloat162 h = __floats2bfloat162_rn(x, y);   // .x = low half
    return *reinterpret_cast<uint*>(&h);
}

__device__ __forceinline__ void mma_bf16(float* d, const uint* a, const uint* b) {
    asm volatile(
        "mma.sync.aligned.m16n8k16.row.col.f32.bf16.bf16.f32 "
        "{%0,%1,%2,%3}, {%4,%5,%6,%7}, {%8,%9}, {%0,%1,%2,%3};"
        : "+f"(d[0]), "+f"(d[1]), "+f"(d[2]), "+f"(d[3])
        : "r"(a[0]), "r"(a[1]), "r"(a[2]), "r"(a[3]), "r"(b[0]), "r"(b[1]));
}

// block-cooperative exclusive scan of g_aux[0..nb) into s[0..255]
__device__ __forceinline__ void scan_aux_block(int* s, int nb) {
    int v = (threadIdx.x < nb) ? g_aux[threadIdx.x] : 0;
    s[threadIdx.x] = v;
    __syncthreads();
#pragma unroll
    for (int dlt = 1; dlt < 256; dlt <<= 1) {
        int tv = (threadIdx.x >= dlt) ? s[threadIdx.x - dlt] : 0;
        __syncthreads();
        s[threadIdx.x] += tv;
        __syncthreads();
    }
    int excl = s[threadIdx.x] - v;
    __syncthreads();
    s[threadIdx.x] = excl;
    __syncthreads();
}

// ---------------------------------------------------------------------------
// Merged prep: blocks [0,128) build g_wn (hi/lo split of W^T rows);
// blocks [128,...) zero counts/cursors.
// ---------------------------------------------------------------------------
__global__ void prep_kernel(const float* __restrict__ Wsrc,
                            const float* __restrict__ Wdst, int Nd) {
    int b = blockIdx.x;
    if (b < 128) {
        int idx = b * 256 + threadIdx.x;      // 0..32767
        int sel = idx >> 14;
        int rem = idx & 16383;
        int n = rem >> 7, k = rem & 127;
        const float* W = sel ? Wdst : Wsrc;
        float w = W[(size_t)k * 128 + n];
        __nv_bfloat16 hi = __float2bfloat16_rn(w);
        __nv_bfloat16 lo = __float2bfloat16_rn(w - __bfloat162float(hi));
        __nv_bfloat16* B = g_wn + (size_t)sel * 128 * 256 + (size_t)n * 256;
        B[k] = hi; B[128 + k] = lo;
    } else {
        int i = (b - 128) * 256 + threadIdx.x;
        if (i < Nd) { g_counts[i] = 0; g_cursors[i] = 0; }
    }
}

// ---------------------------------------------------------------------------
// Tensor-core GEMM (both matrices; sel = blockIdx.y) + fused dst histogram
// tail. Round-13-validated inner loop (scalar frag loads, stride-40 smem).
// ---------------------------------------------------------------------------
struct __align__(16) GemmSmem {
    __nv_bfloat16 Ah[128][40];
    __nv_bfloat16 Al[128][40];
    __nv_bfloat16 Bh[128][40];
    __nv_bfloat16 Bl[128][40];
};

__global__ __launch_bounds__(256, 2) void gemm_mma_kernel(
    const float* __restrict__ featS, const float* __restrict__ featD,
    const float* __restrict__ biasS, const float* __restrict__ biasD,
    const float* __restrict__ attn, const int* __restrict__ d_raw,
    int Ns, int Nd, int E) {
    __shared__ GemmSmem sm;
    __shared__ int s64d;
    int sel = blockIdx.y;
    const float* A = sel ? featD : featS;
    const float* bias = sel ? biasD : biasS;
    int M = sel ? Nd : Ns;
    float* elout = sel ? g_er : g_el;
    int aoff = sel ? 16 : 0;

    int tid = threadIdx.x;
    int wid = tid >> 5;
    int lane = tid & 31;
    int g = lane >> 2;        // row/col group within fragment
    int t = lane & 3;         // pair index
    int trow = 32 * (wid & 3);            // warp row base (local)
    int m0 = blockIdx.x * 128 + trow;     // warp row base (global)
    int n0 = 64 * (wid >> 2);

    int fr = tid >> 1;
    int fh = tid & 1;
    int agr = blockIdx.x * 128 + fr;
    if (agr > M - 1) agr = M - 1;         // clamp: rows valid, stores guarded
    const float* aRow = A + (size_t)agr * 128;
    const __nv_bfloat16* wRow = g_wn + (size_t)sel * 128 * 256 + (size_t)fr * 256;

    if (tid == 0) {
        int any = 0;
#pragma unroll
        for (int i = 1; i < 128; i += 2) any |= __ldg(d_raw + i);
        s64d = (any == 0) ? 1 : 0;
    }

    float acc[2][8][4];
#pragma unroll
    for (int mi = 0; mi < 2; mi++)
#pragma unroll
        for (int ni = 0; ni < 8; ni++)
#pragma unroll
            for (int j = 0; j < 4; j++) acc[mi][ni][j] = 0.f;

    for (int c = 0; c < 4; ++c) {
        __syncthreads();
        {   // ---- fill A (fp32 -> hi/lo bf16) ----
            const float* p = aRow + 32 * c + 16 * fh;
            uint hu[8], lu[8];
#pragma unroll
            for (int q = 0; q < 4; q++) {
                float4 v = *(const float4*)(p + 4 * q);
                float hx = __bfloat162float(__float2bfloat16_rn(v.x));
                float hy = __bfloat162float(__float2bfloat16_rn(v.y));
                float hz = __bfloat162float(__float2bfloat16_rn(v.z));
                float hw = __bfloat162float(__float2bfloat16_rn(v.w));
                hu[2 * q]     = pack_bf2(v.x, v.y);
                hu[2 * q + 1] = pack_bf2(v.z, v.w);
                lu[2 * q]     = pack_bf2(v.x - hx, v.y - hy);
                lu[2 * q + 1] = pack_bf2(v.z - hz, v.w - hw);
            }
            *(uint4*)&sm.Ah[fr][16 * fh]     = *(uint4*)&hu[0];
            *(uint4*)&sm.Ah[fr][16 * fh + 8] = *(uint4*)&hu[4];
            *(uint4*)&sm.Al[fr][16 * fh]     = *(uint4*)&lu[0];
            *(uint4*)&sm.Al[fr][16 * fh + 8] = *(uint4*)&lu[4];
        }
        {   // ---- fill B (copy prepped bf16) ----
            const __nv_bfloat16* ph = wRow + 32 * c + 16 * fh;
            const __nv_bfloat16* pl = ph + 128;
            *(uint4*)&sm.Bh[fr][16 * fh]     = *(const uint4*)ph;
            *(uint4*)&sm.Bh[fr][16 * fh + 8] = *(const uint4*)(ph + 8);
            *(uint4*)&sm.Bl[fr][16 * fh]     = *(const uint4*)pl;
            *(uint4*)&sm.Bl[fr][16 * fh + 8] = *(const uint4*)(pl + 8);
        }
        __syncthreads();
#pragma unroll
        for (int ks = 0; ks < 2; ks++) {
            int kb = 16 * ks;
            uint ah[2][4], al[2][4];
#pragma unroll
            for (int mi = 0; mi < 2; mi++)
#pragma unroll
                for (int j = 0; j < 4; j++) {
                    int r = trow + 16 * mi + 8 * (j & 1) + g;
                    int col = kb + 2 * t + 8 * (j >> 1);
                    ah[mi][j] = *(const uint*)&sm.Ah[r][col];
                    al[mi][j] = *(const uint*)&sm.Al[r][col];
                }
#pragma unroll
            for (int ni = 0; ni < 8; ni++) {
                int n = n0 + 8 * ni + g;
                uint bh[2], bl[2];
                bh[0] = *(const uint*)&sm.Bh[n][kb + 2 * t];
                bh[1] = *(const uint*)&sm.Bh[n][kb + 2 * t + 8];
                bl[0] = *(const uint*)&sm.Bl[n][kb + 2 * t];
                bl[1] = *(const uint*)&sm.Bl[n][kb + 2 * t + 8];
#pragma unroll
                for (int mi = 0; mi < 2; mi++) {
                    mma_bf16(acc[mi][ni], ah[mi], bh);
                    mma_bf16(acc[mi][ni], al[mi], bh);
                    mma_bf16(acc[mi][ni], ah[mi], bl);
                }
            }
        }
    }

    // ---- epilogue (validated layout) ----
    float2 bvals[8];
#pragma unroll
    for (int ni = 0; ni < 8; ni++)
        bvals[ni] = *(const float2*)(bias + n0 + 8 * ni + 2 * t);
    float2 awlo[4], awhi[4];
#pragma unroll
    for (int h = 0; h < 4; h++) {
        const float* ab = attn + (size_t)((n0 >> 4) + h) * 32 + aoff;
        awlo[h] = *(const float2*)(ab + 2 * t);
        awhi[h] = *(const float2*)(ab + 8 + 2 * t);
    }

#pragma unroll
    for (int mi = 0; mi < 2; mi++) {
#pragma unroll
        for (int hh = 0; hh < 2; hh++) {
            int r = m0 + 16 * mi + 8 * hh + g;
            int j0 = hh * 2;
            float v[8][2];
#pragma unroll
            for (int ni = 0; ni < 8; ni++) {
                v[ni][0] = acc[mi][ni][j0] + bvals[ni].x;
                v[ni][1] = acc[mi][ni][j0 + 1] + bvals[ni].y;
            }
            float p[4];
#pragma unroll
            for (int h = 0; h < 4; h++) {
                p[h] = v[2 * h][0] * awlo[h].x + v[2 * h][1] * awlo[h].y +
                       v[2 * h + 1][0] * awhi[h].x + v[2 * h + 1][1] * awhi[h].y;
                p[h] += __shfl_xor_sync(0xffffffffu, p[h], 1);
                p[h] += __shfl_xor_sync(0xffffffffu, p[h], 2);
            }
            if (r < M) {
                if (sel == 0) {
#pragma unroll
                    for (int ni = 0; ni < 8; ni++) {
                        __half2 hv = __floats2half2_rn(v[ni][0], v[ni][1]);
                        *(uint*)(g_hs_h + (size_t)r * 128 + n0 + 8 * ni + 2 * t) =
                            *reinterpret_cast<uint*>(&hv);
                    }
                }
                if (t == 0) {
#pragma unroll
                    for (int h = 0; h < 4; h++)
                        elout[(size_t)r * 8 + (n0 >> 4) + h] = p[h];
                }
            }
        }
    }

    // ---- fused dst histogram (grid-stride tail, int4-vectorized) ----
    __syncthreads();   // s64d visible; smem work done
    int gtid = (blockIdx.y * gridDim.x + blockIdx.x) * 256 + tid;
    int stride = gridDim.x * gridDim.y * 256;
    if (!s64d) {
        int nvec = E >> 2;
        const int4* d4p = (const int4*)d_raw;
        for (int e4 = gtid; e4 < nvec; e4 += stride) {
            int4 d4 = __ldg(d4p + e4);
            atomicAdd(&g_counts[d4.x], 1);
            atomicAdd(&g_counts[d4.y], 1);
            atomicAdd(&g_counts[d4.z], 1);
            atomicAdd(&g_counts[d4.w], 1);
        }
        for (int e = (nvec << 2) + gtid; e < E; e += stride)
            atomicAdd(&g_counts[d_raw[e]], 1);
    } else {
        for (int e = gtid; e < E; e += stride) {
            int d = (int)(((const long long*)d_raw)[e]);
            atomicAdd(&g_counts[d], 1);
        }
    }
}

// ---------------------------------------------------------------------------
// scan1: per-256-block exclusive scan of counts + block sums into g_aux.
// Consumers add the aux prefix themselves (scan_aux_block).
// ---------------------------------------------------------------------------
__global__ void scan1_kernel(int n) {
    __shared__ int s[256];
    int i = blockIdx.x * 256 + threadIdx.x;
    int v = (i < n) ? g_counts[i] : 0;
    s[threadIdx.x] = v;
    __syncthreads();
#pragma unroll
    for (int dlt = 1; dlt < 256; dlt <<= 1) {
        int tv = (threadIdx.x >= dlt) ? s[threadIdx.x - dlt] : 0;
        __syncthreads();
        s[threadIdx.x] += tv;
        __syncthreads();
    }
    if (i < n) g_offsets[i] = s[threadIdx.x] - v;
    if (threadIdx.x == 255) g_aux[blockIdx.x] = s[255];
}

// ---------------------------------------------------------------------------
// scatter: thread-per-4-edges, int4 idx loads (int32 path); adds aux prefix.
// ---------------------------------------------------------------------------
__global__ void scatter_kernel(const int* __restrict__ s_raw,
                               const int* __restrict__ d_raw, int E, int nb) {
    __shared__ int sAux[256];
    __shared__ int s64s, s64d;
    if (threadIdx.x == 0) {
        int any = 0;
#pragma unroll
        for (int i = 1; i < 128; i += 2) any |= __ldg(s_raw + i);
        s64s = (any == 0) ? 1 : 0;
        any = 0;
#pragma unroll
        for (int i = 1; i < 128; i += 2) any |= __ldg(d_raw + i);
        s64d = (any == 0) ? 1 : 0;
    }
    scan_aux_block(sAux, nb);   // includes the syncthreads that publishes s64*

    int base = (blockIdx.x * 256 + threadIdx.x) * 4;
    if (base >= E) return;
    if (!s64s && !s64d && base + 4 <= E) {
        int4 s4 = __ldg((const int4*)(s_raw + base));
        int4 d4 = __ldg((const int4*)(d_raw + base));
        int ss[4] = {s4.x, s4.y, s4.z, s4.w};
        int dd[4] = {d4.x, d4.y, d4.z, d4.w};
#pragma unroll
        for (int j = 0; j < 4; j++) {
            int d = dd[j];
            int pos = g_offsets[d] + sAux[d >> 8] + atomicAdd(&g_cursors[d], 1);
            g_sorted_src[pos] = ss[j];
        }
    } else {
        for (int e = base; e < base + 4 && e < E; ++e) {
            int s = s64s ? (int)(((const long long*)s_raw)[e]) : s_raw[e];
            int d = s64d ? (int)(((const long long*)d_raw)[e]) : d_raw[e];
            int pos = g_offsets[d] + sAux[d >> 8] + atomicAdd(&g_cursors[d], 1);
            g_sorted_src[pos] = s;
        }
    }
}

// ---------------------------------------------------------------------------
// Fused softmax + aggregation: one warp per dst, 4-edge groups with one
// int4 idx load each (peeled to 16B alignment). Adds aux prefix per block.
// fp16 message gather, fp32 accumulate.
// ---------------------------------------------------------------------------
__global__ __launch_bounds__(256) void agg_kernel(float* __restrict__ out,
                                                  int Nd, int nb) {
    __shared__ int sAux[256];
    scan_aux_block(sAux, nb);

    int wpb = blockDim.x >> 5;
    int d = blockIdx.x * wpb + (threadIdx.x >> 5);
    if (d >= Nd) return;
    int lane = threadIdx.x & 31;
    int k = lane >> 2;

    int off = g_offsets[d] + sAux[d >> 8];
    int n = g_counts[d];
    float er_k = g_er[(size_t)d * 8 + k];

    float a0 = 0.f, a1 = 0.f, a2 = 0.f, a3 = 0.f;
    float wsum = 0.f;
    const int* srcp = g_sorted_src + off;
    int i = 0;
    int peel = (4 - (off & 3)) & 3;          // to 16B alignment
    if (peel > n) peel = n;
    for (; i < peel; ++i) {
        int s0 = __ldg(srcp + i);
        float w0 = __expf(lrelu(g_el[(size_t)s0 * 8 + k] + er_k));
        uint2 v0 = *(const uint2*)(g_hs_h + (size_t)s0 * 128 + (lane << 2));
        float2 f00 = __half22float2(*reinterpret_cast<__half2*>(&v0.x));
        float2 f01 = __half22float2(*reinterpret_cast<__half2*>(&v0.y));
        wsum += w0;
        a0 += f00.x * w0; a1 += f00.y * w0; a2 += f01.x * w0; a3 += f01.y * w0;
    }
    for (; i + 4 <= n; i += 4) {
        int4 s4 = __ldg((const int4*)(srcp + i));
        float w0 = __expf(lrelu(g_el[(size_t)s4.x * 8 + k] + er_k));
        float w1 = __expf(lrelu(g_el[(size_t)s4.y * 8 + k] + er_k));
        float w2 = __expf(lrelu(g_el[(size_t)s4.z * 8 + k] + er_k));
        float w3 = __expf(lrelu(g_el[(size_t)s4.w * 8 + k] + er_k));
        uint2 v0 = *(const uint2*)(g_hs_h + (size_t)s4.x * 128 + (lane << 2));
        uint2 v1 = *(const uint2*)(g_hs_h + (size_t)s4.y * 128 + (lane << 2));
        uint2 v2 = *(const uint2*)(g_hs_h + (size_t)s4.z * 128 + (lane << 2));
        uint2 v3 = *(const uint2*)(g_hs_h + (size_t)s4.w * 128 + (lane << 2));
        float2 f00 = __half22float2(*reinterpret_cast<__half2*>(&v0.x));
        float2 f01 = __half22float2(*reinterpret_cast<__half2*>(&v0.y));
        float2 f10 = __half22float2(*reinterpret_cast<__half2*>(&v1.x));
        float2 f11 = __half22float2(*reinterpret_cast<__half2*>(&v1.y));
        float2 f20 = __half22float2(*reinterpret_cast<__half2*>(&v2.x));
        float2 f21 = __half22float2(*reinterpret_cast<__half2*>(&v2.y));
        float2 f30 = __half22float2(*reinterpret_cast<__half2*>(&v3.x));
        float2 f31 = __half22float2(*reinterpret_cast<__half2*>(&v3.y));
        wsum += w0; wsum += w1; wsum += w2; wsum += w3;
        a0 += f00.x * w0; a1 += f00.y * w0; a2 += f01.x * w0; a3 += f01.y * w0;
        a0 += f10.x * w1; a1 += f10.y * w1; a2 += f11.x * w1; a3 += f11.y * w1;
        a0 += f20.x * w2; a1 += f20.y * w2; a2 += f21.x * w2; a3 += f21.y * w2;
        a0 += f30.x * w3; a1 += f30.y * w3; a2 += f31.x * w3; a3 += f31.y * w3;
    }
    for (; i < n; ++i) {
        int s0 = __ldg(srcp + i);
        float w0 = __expf(lrelu(g_el[(size_t)s0 * 8 + k] + er_k));
        uint2 v0 = *(const uint2*)(g_hs_h + (size_t)s0 * 128 + (lane << 2));
        float2 f00 = __half22float2(*reinterpret_cast<__half2*>(&v0.x));
        float2 f01 = __half22float2(*reinterpret_cast<__half2*>(&v0.y));
        wsum += w0;
        a0 += f00.x * w0; a1 += f00.y * w0; a2 += f01.x * w0; a3 += f01.y * w0;
    }
    float inv = (wsum > 0.f) ? __fdividef(1.f, wsum) : 0.f;
    *(float4*)(out + (size_t)d * 128 + (lane << 2)) =
        make_float4(a0 * inv, a1 * inv, a2 * inv, a3 * inv);
}

// ---------------------------------------------------------------------------
extern "C" void kernel_launch(void* const* d_in, const int* in_sizes, int n_in,
                              void* d_out, int out_size) {
    const float* feat_src = (const float*)d_in[0];
    const float* feat_dst = (const float*)d_in[1];
    const float* W_src    = (const float*)d_in[2];
    const float* b_src    = (const float*)d_in[3];
    const float* W_dst    = (const float*)d_in[4];
    const float* b_dst    = (const float*)d_in[5];
    const float* attn     = (const float*)d_in[6];
    const int*   src_raw  = (const int*)d_in[7];
    const int*   dst_raw  = (const int*)d_in[8];
    float* out = (float*)d_out;

    int Ns = in_sizes[0] / 128;
    int Nd = in_sizes[1] / 128;
    if (Ns > NSRC) Ns = NSRC;
    if (Nd > NDST) Nd = NDST;
    int E = in_sizes[7];
    if (E > EMAX) E = EMAX;

    // prep_w (128 blocks) + zero counts/cursors
    prep_kernel<<<128 + (Nd + 255) / 256, 256>>>(W_src, W_dst, Nd);

    // both GEMMs + fused dst histogram in one launch
    int nblk = ((Ns > Nd ? Ns : Nd) + 127) / 128;
    dim3 ggrid(nblk, 2);
    gemm_mma_kernel<<<ggrid, 256>>>(feat_src, feat_dst, b_src, b_dst,
                                    attn, dst_raw, Ns, Nd, E);

    int nb = (Nd + 255) / 256;
    scan1_kernel<<<nb, 256>>>(Nd);
    scatter_kernel<<<(E + 1023) / 1024, 256>>>(src_raw, dst_raw, E, nb);

    agg_kernel<<<(Nd + 7) / 8, 256>>>(out, Nd, nb);
}